// round 4
// baseline (speedup 1.0000x reference)
#include <cuda_runtime.h>
#include <cstdint>

#define BATCH    64
#define SEQ      8192
#define RDIM     80
#define NTAPS    5
#define MAXD     168
#define RING     169          // write slot disjoint from all read slots mod 169
#define NTHREADS 320          // lane map: jh = tid&3 (j-quarter), i = tid>>2
#define JSLICE   20
#define NPAIR    10           // f32x2 pairs per tap per thread

typedef unsigned long long u64;

__device__ __forceinline__ u64 ffma2(u64 a, u64 b, u64 c) {
    u64 d;
    asm("fma.rn.f32x2 %0, %1, %2, %3;" : "=l"(d) : "l"(a), "l"(b), "l"(c));
    return d;
}

__device__ __forceinline__ float2 unpack2(u64 v) {
    unsigned lo, hi;
    asm("mov.b64 {%0, %1}, %2;" : "=r"(lo), "=r"(hi) : "l"(v));
    float2 r;
    r.x = __uint_as_float(lo);
    r.y = __uint_as_float(hi);
    return r;
}

__device__ __forceinline__ float fast_tanh(float v) {
    v = fminf(fmaxf(v, -15.0f), 15.0f);
    float u = __expf(-2.0f * v);                 // 1 FMA + MUFU.EX2
    return __fdividef(1.0f - u, 1.0f + u);       // MUFU.RCP + MUL
}

// Accumulate one tap row (20 floats at hrow) against Wp[k][*]
#define TAP_ACC(k, hrow)                                                  \
    do {                                                                  \
        const ulonglong2* hv = reinterpret_cast<const ulonglong2*>(hrow); \
        ulonglong2 h01 = hv[0];                                           \
        ulonglong2 h23 = hv[1];                                           \
        ulonglong2 h45 = hv[2];                                           \
        ulonglong2 h67 = hv[3];                                           \
        ulonglong2 h89 = hv[4];                                           \
        a0 = ffma2(h01.x, Wp[k][0], a0);                                  \
        a1 = ffma2(h01.y, Wp[k][1], a1);                                  \
        a2 = ffma2(h23.x, Wp[k][2], a2);                                  \
        a3 = ffma2(h23.y, Wp[k][3], a3);                                  \
        a0 = ffma2(h45.x, Wp[k][4], a0);                                  \
        a1 = ffma2(h45.y, Wp[k][5], a1);                                  \
        a2 = ffma2(h67.x, Wp[k][6], a2);                                  \
        a3 = ffma2(h67.y, Wp[k][7], a3);                                  \
        a0 = ffma2(h89.x, Wp[k][8], a0);                                  \
        a1 = ffma2(h89.y, Wp[k][9], a1);                                  \
    } while (0)

__global__ __launch_bounds__(NTHREADS, 1)
void reservoir_kernel(const float* __restrict__ x,
                      const float* __restrict__ Win,
                      const float* __restrict__ Wfb,
                      const float* __restrict__ bias,
                      float* __restrict__ out)
{
    extern __shared__ float sm[];
    float* Hring = sm;                     // [RING][RDIM] = 13520 f
    float* xs    = Hring + RING * RDIM;    // [SEQ]        = 8192 f

    const int b   = blockIdx.x;
    const int tid = threadIdx.x;
    const int jh  = tid & 3;               // j-quarter (adjacent lanes)
    const int i   = tid >> 2;              // reservoir neuron 0..79

    for (int idx = tid; idx < RING * RDIM; idx += NTHREADS) Hring[idx] = 0.0f;

    const float* xb = x + (size_t)b * SEQ;
    for (int idx = tid; idx < SEQ; idx += NTHREADS) xs[idx] = xb[idx];

    // feedback[i] = sum_k sum_j delayed[k][j] * Wfb[k][i][j]
    u64 Wp[NTAPS][NPAIR];
#pragma unroll
    for (int k = 0; k < NTAPS; k++) {
        const float* wrow = Wfb + ((size_t)k * RDIM + i) * RDIM + jh * JSLICE;
#pragma unroll
        for (int p = 0; p < NPAIR; p++) {
            unsigned lo = __float_as_uint(wrow[2 * p]);
            unsigned hi = __float_as_uint(wrow[2 * p + 1]);
            Wp[k][p] = ((u64)hi << 32) | (u64)lo;
        }
    }

    const float win_i  = Win[i];
    const float bias_i = bias[i];
    float h_i = 0.0f;

    float* outb = out + (size_t)b * SEQ * RDIM;
    const float* hbase = Hring + jh * JSLICE;

    // Ring slots at t=0: write w = 0; read r_k = (0 - tau_k) mod 169
    int w  = 0;
    int r0 = RING - 1;    // tau 1
    int r1 = RING - 4;    // tau 4
    int r2 = RING - 24;   // tau 24
    int r3 = RING - 96;   // tau 96
    int r4 = RING - 168;  // tau 168

    __syncthreads();

#pragma unroll 1
    for (int t = 0; t < SEQ; ++t) {
        u64 a0 = 0ull, a1 = 0ull, a2 = 0ull, a3 = 0ull;

        // ---- P1: taps {4,24,96,168} — need only h[t-4] and older, which
        // became visible at BAR(t-3) or earlier. Overlaps with other warps
        // still finishing step t-1's post-barrier region.
        TAP_ACC(1, hbase + r1 * RDIM);
        TAP_ACC(2, hbase + r2 * RDIM);
        TAP_ACC(3, hbase + r3 * RDIM);
        TAP_ACC(4, hbase + r4 * RDIM);

        const float x_t = xs[t];   // prefetched before the barrier

        // ---- single BAR per step: publishes h[t-1]
        __syncthreads();

        // ---- tap 1 (needs h[t-1]) + in-warp reduce + update
        TAP_ACC(0, hbase + r0 * RDIM);

        float2 f0 = unpack2(a0);
        float2 f1 = unpack2(a1);
        float2 f2 = unpack2(a2);
        float2 f3 = unpack2(a3);
        float f = ((f0.x + f0.y) + (f1.x + f1.y)) +
                  ((f2.x + f2.y) + (f3.x + f3.y));

        // butterfly over the 4 j-quarter lanes of this neuron
        f += __shfl_xor_sync(0xffffffffu, f, 1);
        f += __shfl_xor_sync(0xffffffffu, f, 2);

        // all 4 lanes compute the identical update (no divergence)
        float val = fmaf(x_t, win_i, f + bias_i);
        h_i = 0.7f * h_i + 0.3f * fast_tanh(val);

        if (jh == 0) {
            Hring[w * RDIM + i] = h_i;          // 8 words/warp, conflict-free
            outb[(size_t)t * RDIM + i] = h_i;   // coalesced 32B/warp
        }

        ++w;  if (w  == RING) w  = 0;
        ++r0; if (r0 == RING) r0 = 0;
        ++r1; if (r1 == RING) r1 = 0;
        ++r2; if (r2 == RING) r2 = 0;
        ++r3; if (r3 == RING) r3 = 0;
        ++r4; if (r4 == RING) r4 = 0;
    }
}

extern "C" void kernel_launch(void* const* d_in, const int* in_sizes, int n_in,
                              void* d_out, int out_size)
{
    const float* x    = (const float*)d_in[0];  // [64, 8192, 1]
    const float* Win  = (const float*)d_in[1];  // [80, 1]
    const float* Wfb  = (const float*)d_in[2];  // [5, 80, 80]
    const float* bias = (const float*)d_in[3];  // [80]
    float* out = (float*)d_out;                 // [64, 8192, 80]

    const int smem_bytes = (RING * RDIM + SEQ) * sizeof(float);
    cudaFuncSetAttribute(reservoir_kernel,
                         cudaFuncAttributeMaxDynamicSharedMemorySize, smem_bytes);

    reservoir_kernel<<<BATCH, NTHREADS, smem_bytes>>>(x, Win, Wfb, bias, out);
}

// round 6
// speedup vs baseline: 1.1568x; 1.1568x over previous
#include <cuda_runtime.h>
#include <cstdint>

#define BATCH    64
#define SEQ      8192
#define RDIM     80
#define MAXD     168
#define RING     169
#define NTHREADS 320
#define JSLICE   20
#define NPAIR    10          // f32x2 pairs per old-tap per thread (20 floats)
#define YPAIR    20          // f32x2 pairs per tau=1 half-row (40 floats)

typedef unsigned long long u64;

__device__ __forceinline__ u64 ffma2(u64 a, u64 b, u64 c) {
    u64 d;
    asm("fma.rn.f32x2 %0, %1, %2, %3;" : "=l"(d) : "l"(a), "l"(b), "l"(c));
    return d;
}

__device__ __forceinline__ float2 unpack2(u64 v) {
    unsigned lo, hi;
    asm("mov.b64 {%0, %1}, %2;" : "=r"(lo), "=r"(hi) : "l"(v));
    float2 r;
    r.x = __uint_as_float(lo);
    r.y = __uint_as_float(hi);
    return r;
}

__device__ __forceinline__ float fast_tanh(float v) {
    v = fminf(fmaxf(v, -15.0f), 15.0f);
    float u = __expf(-2.0f * v);
    return __fdividef(1.0f - u, 1.0f + u);
}

// Accumulate one old-tap row (20 floats at hrow) against Wo[k][*]
#define TAP_ACC(k, hrow)                                                  \
    do {                                                                  \
        const ulonglong2* hv = reinterpret_cast<const ulonglong2*>(hrow); \
        ulonglong2 h01 = hv[0];                                           \
        ulonglong2 h23 = hv[1];                                           \
        ulonglong2 h45 = hv[2];                                           \
        ulonglong2 h67 = hv[3];                                           \
        ulonglong2 h89 = hv[4];                                           \
        a0 = ffma2(h01.x, Wo[k][0], a0);                                  \
        a1 = ffma2(h01.y, Wo[k][1], a1);                                  \
        a2 = ffma2(h23.x, Wo[k][2], a2);                                  \
        a3 = ffma2(h23.y, Wo[k][3], a3);                                  \
        a0 = ffma2(h45.x, Wo[k][4], a0);                                  \
        a1 = ffma2(h45.y, Wo[k][5], a1);                                  \
        a2 = ffma2(h67.x, Wo[k][6], a2);                                  \
        a3 = ffma2(h67.y, Wo[k][7], a3);                                  \
        a0 = ffma2(h89.x, Wo[k][8], a0);                                  \
        a1 = ffma2(h89.y, Wo[k][9], a1);                                  \
    } while (0)

__global__ __launch_bounds__(NTHREADS, 1)
void reservoir_kernel(const float* __restrict__ x,
                      const float* __restrict__ Win,
                      const float* __restrict__ Wfb,
                      const float* __restrict__ bias,
                      float* __restrict__ out)
{
    extern __shared__ float sm[];
    float* Hring = sm;                     // [RING][RDIM]  = 13520 f
    float* xs    = Hring + RING * RDIM;    // [SEQ]         = 8192 f
    float* part  = xs + SEQ;               // [4][NTHREADS] = 1280 f

    const int b   = blockIdx.x;
    const int tid = threadIdx.x;

    // --- X identity (old-tap partials): jx = j-quarter, ix = neuron
    const int jx = tid & 3;
    const int ix = tid >> 2;

    // --- Y identity (tau=1 + epilogue), tid < 160: iy = neuron, hy = j-half
    const int iy = tid >> 1;
    const int hy = tid & 1;

    for (int idx = tid; idx < RING * RDIM; idx += NTHREADS) Hring[idx] = 0.0f;
    for (int idx = tid; idx < 4 * NTHREADS; idx += NTHREADS) part[idx] = 0.0f;

    const float* xb = x + (size_t)b * SEQ;
    for (int idx = tid; idx < SEQ; idx += NTHREADS) xs[idx] = xb[idx];

    // Old-tap weights (taps 4,24,96,168 = Wfb[1..4]) for (ix, jx) slice
    u64 Wo[4][NPAIR];
#pragma unroll
    for (int k = 0; k < 4; k++) {
        const float* wrow = Wfb + ((size_t)(k + 1) * RDIM + ix) * RDIM + jx * JSLICE;
#pragma unroll
        for (int p = 0; p < NPAIR; p++) {
            unsigned lo = __float_as_uint(wrow[2 * p]);
            unsigned hi = __float_as_uint(wrow[2 * p + 1]);
            Wo[k][p] = ((u64)hi << 32) | (u64)lo;
        }
    }

    // tau=1 weights (Wfb[0]) half-row (40 floats = 20 pairs) for (iy, hy)
    u64 W1[YPAIR];
    float win_i = 0.0f, bias_i = 0.0f, h_i = 0.0f;
    if (tid < 2 * RDIM) {
        const float* wrow = Wfb + (size_t)iy * RDIM + hy * 40;
#pragma unroll
        for (int p = 0; p < YPAIR; p++) {
            unsigned lo = __float_as_uint(wrow[2 * p]);
            unsigned hi = __float_as_uint(wrow[2 * p + 1]);
            W1[p] = ((u64)hi << 32) | (u64)lo;
        }
        win_i  = Win[iy];
        bias_i = bias[iy];
    }

    float* outb = out + (size_t)b * SEQ * RDIM;

    // Ring slots at t=0 (mod 169): write w=0, reads at t-1, t-21, t-93, t-165
    int w    = 0;
    int rm1  = RING - 1;     // t-1   (tau=1 read AND tau=4-for-step-t+3 read)
    int rm21 = RING - 21;    // t-21  (tau=24 for step t+3)
    int rm93 = RING - 93;    // t-93  (tau=96 for step t+3)
    int rm165= RING - 165;   // t-165 (tau=168 for step t+3)

    __syncthreads();

#pragma unroll 1
    for (int t = 0; t < SEQ; ++t) {
        const float* hprev = Hring + rm1 * RDIM;   // h[t-1]

        // ===== Y: step t update (threads 0..159) — critical path =====
        if (tid < 2 * RDIM) {
            // tau=1 half matvec (40 j-values): broadcast reads of h[t-1]
            const ulonglong2* hv =
                reinterpret_cast<const ulonglong2*>(hprev + hy * 40);
            u64 y0 = 0ull, y1 = 0ull, y2 = 0ull, y3 = 0ull;
#pragma unroll
            for (int p = 0; p < 5; p++) {
                ulonglong2 ga = hv[2 * p];
                ulonglong2 gb = hv[2 * p + 1];
                y0 = ffma2(ga.x, W1[4 * p + 0], y0);
                y1 = ffma2(ga.y, W1[4 * p + 1], y1);
                y2 = ffma2(gb.x, W1[4 * p + 2], y2);
                y3 = ffma2(gb.y, W1[4 * p + 3], y3);
            }

            float2 q0 = unpack2(y0);
            float2 q1 = unpack2(y1);
            float2 q2 = unpack2(y2);
            float2 q3 = unpack2(y3);
            float fh = ((q0.x + q0.y) + (q1.x + q1.y)) +
                       ((q2.x + q2.y) + (q3.x + q3.y));
            // combine the two j-halves (adjacent lanes)
            fh += __shfl_xor_sync(0xffffffffu, fh, 1);

            // old-tap partials for step t (written 3 iters ago)
            float4 p4 = *reinterpret_cast<const float4*>(
                part + (t & 3) * NTHREADS + 4 * iy);
            float f = fh + ((p4.x + p4.y) + (p4.z + p4.w));

            float val = fmaf(xs[t], win_i, f + bias_i);
            h_i = 0.7f * h_i + 0.3f * fast_tanh(val);

            if (hy == 0) {
                Hring[w * RDIM + iy] = h_i;          // slot t
                outb[(size_t)t * RDIM + iy] = h_i;
            }
        }

        // ===== X: old-tap partials for step t+3 (all 320 threads) =====
        // taps {4,24,96,168} for step t+3 read h[t-1], h[t-21], h[t-93], h[t-165]
        {
            u64 a0 = 0ull, a1 = 0ull, a2 = 0ull, a3 = 0ull;
            const float* hb = Hring + jx * JSLICE;
            TAP_ACC(0, hb + rm1   * RDIM);
            TAP_ACC(1, hb + rm21  * RDIM);
            TAP_ACC(2, hb + rm93  * RDIM);
            TAP_ACC(3, hb + rm165 * RDIM);
            float2 f0 = unpack2(a0);
            float2 f1 = unpack2(a1);
            float2 f2 = unpack2(a2);
            float2 f3 = unpack2(a3);
            part[((t + 3) & 3) * NTHREADS + ix * 4 + jx] =
                ((f0.x + f0.y) + (f1.x + f1.y)) + ((f2.x + f2.y) + (f3.x + f3.y));
        }

        // advance ring counters (mod 169)
        ++w;     if (w     == RING) w     = 0;
        ++rm1;   if (rm1   == RING) rm1   = 0;
        ++rm21;  if (rm21  == RING) rm21  = 0;
        ++rm93;  if (rm93  == RING) rm93  = 0;
        ++rm165; if (rm165 == RING) rm165 = 0;

        // single barrier: publishes h[t] (Y) and partials for step t+3 (X)
        __syncthreads();
    }
}

extern "C" void kernel_launch(void* const* d_in, const int* in_sizes, int n_in,
                              void* d_out, int out_size)
{
    const float* x    = (const float*)d_in[0];  // [64, 8192, 1]
    const float* Win  = (const float*)d_in[1];  // [80, 1]
    const float* Wfb  = (const float*)d_in[2];  // [5, 80, 80]
    const float* bias = (const float*)d_in[3];  // [80]
    float* out = (float*)d_out;                 // [64, 8192, 80]

    const int smem_bytes = (RING * RDIM + SEQ + 4 * NTHREADS) * sizeof(float);
    cudaFuncSetAttribute(reservoir_kernel,
                         cudaFuncAttributeMaxDynamicSharedMemorySize, smem_bytes);

    reservoir_kernel<<<BATCH, NTHREADS, smem_bytes>>>(x, Win, Wfb, bias, out);
}